// round 16
// baseline (speedup 1.0000x reference)
#include <cuda_runtime.h>
#include <cuda_bf16.h>
#include <mma.h>
#include <math.h>
#include <stdint.h>

using namespace nvcuda;

#define NN 50000
#define NPAD 50176   // padded rows: plane tiles never read OOB (zero-init padding)
#define EE 800000
#define DH 128
#define DOUT 40
#define WLD 136   // padded leading dim for bf16 tiles (elements)
#define HLD 72    // padded leading dim for head B tile

// ---------------- scratch (device globals; no allocation allowed) ----------------
__device__ float g_bufB[NN * DH];
__device__ float g_bufC[NN * DH];
__device__ __nv_bfloat16 g_pl[2][2][NPAD * DH];   // [set][hi/lo] bf16 planes
__device__ float g_sum[DH];
__device__ float g_sqsum[DH];
__device__ int   g_deg[NN];
__device__ int   g_off[NN + 1];
__device__ int   g_rank[EE];
__device__ int   g_slot[EE];
__device__ __nv_bfloat16 g_Wbf[5][2][128 * WLD];
__device__ __nv_bfloat16 g_Wl2bf[2][128 * HLD];

// ---------------- helpers ----------------
__device__ __forceinline__ unsigned short bfu(float v) {
    __nv_bfloat16 h = __float2bfloat16(v);
    return *reinterpret_cast<unsigned short*>(&h);
}
__device__ __forceinline__ float bff(unsigned short u) {
    __nv_bfloat16 h = *reinterpret_cast<__nv_bfloat16*>(&u);
    return __bfloat162float(h);
}
// split float4 into packed hi (u64 of 4 bf16) and lo
__device__ __forceinline__ void split4(float4 v, unsigned long long& hp, unsigned long long& lp) {
    unsigned short h0 = bfu(v.x), h1 = bfu(v.y), h2 = bfu(v.z), h3 = bfu(v.w);
    unsigned short l0 = bfu(v.x - bff(h0)), l1 = bfu(v.y - bff(h1));
    unsigned short l2 = bfu(v.z - bff(h2)), l3 = bfu(v.w - bff(h3));
    hp = (unsigned long long)h0 | ((unsigned long long)h1 << 16)
       | ((unsigned long long)h2 << 32) | ((unsigned long long)h3 << 48);
    lp = (unsigned long long)l0 | ((unsigned long long)l1 << 16)
       | ((unsigned long long)l2 << 32) | ((unsigned long long)l3 << 48);
}

__device__ __forceinline__ void cp_async16(void* smem_dst, const void* gmem_src) {
    uint32_t s = (uint32_t)__cvta_generic_to_shared(smem_dst);
    asm volatile("cp.async.cg.shared.global [%0], [%1], 16;" :: "r"(s), "l"(gmem_src));
}
__device__ __forceinline__ void cp_async_commit() {
    asm volatile("cp.async.commit_group;" ::: "memory");
}
__device__ __forceinline__ void cp_async_wait_all() {
    asm volatile("cp.async.wait_group 0;" ::: "memory");
}

// ---------------- CSR build ----------------
__global__ void hist_kernel(const int* __restrict__ ei) {
    int e = blockIdx.x * blockDim.x + threadIdx.x;
    if (e >= EE) return;
    int dst = min(max(__ldg(&ei[EE + e]), 0), NN - 1);
    g_rank[e] = atomicAdd(&g_deg[dst], 1);
}

__global__ void __launch_bounds__(1024) scan_kernel() {
    const int CH = (NN + 1023) / 1024;
    int t = threadIdx.x;
    int base = t * CH;
    int s = 0;
    for (int i = 0; i < CH; i++) {
        int idx = base + i;
        if (idx < NN) s += g_deg[idx];
    }
    __shared__ int sh[1024];
    sh[t] = s;
    __syncthreads();
    for (int off = 1; off < 1024; off <<= 1) {
        int v = (t >= off) ? sh[t - off] : 0;
        __syncthreads();
        sh[t] += v;
        __syncthreads();
    }
    int run = sh[t] - s;
    for (int i = 0; i < CH; i++) {
        int idx = base + i;
        if (idx < NN) {
            g_off[idx] = run;
            run += g_deg[idx];
        }
    }
    if (t == 1023) g_off[NN] = run;
}

__global__ void fill_kernel(const int* __restrict__ ei) {
    int e = blockIdx.x * blockDim.x + threadIdx.x;
    if (e >= EE) return;
    int src = min(max(__ldg(&ei[e]), 0), NN - 1);
    int dst = min(max(__ldg(&ei[EE + e]), 0), NN - 1);
    int pos = __ldg(&g_off[dst]) + g_rank[e];
    g_slot[pos] = src;
}

// ---------------- aggregation: warp per node; writes PRE-SPLIT bf16 hi/lo planes ------
// block 0 also zeroes the BN stats accumulators.
__global__ void __launch_bounds__(256) aggregate_kernel(
    const float* __restrict__ X,
    unsigned long long* __restrict__ Phi,    // u64 view: 32 per row
    unsigned long long* __restrict__ Plo) {
    if (blockIdx.x == 0 && threadIdx.x < 128) {
        g_sum[threadIdx.x] = 0.f;
        g_sqsum[threadIdx.x] = 0.f;
    }
    int node = blockIdx.x * 8 + (threadIdx.x >> 5);
    if (node >= NN) return;
    int lane = threadIdx.x & 31;
    const float4* X4 = (const float4*)X;
    float4 a = __ldg(&X4[(size_t)node * 32 + lane]);
    int s = __ldg(&g_off[node]);
    int e = __ldg(&g_off[node + 1]);
    int j = s;
    for (; j + 4 <= e; j += 4) {
        int s0 = __ldg(&g_slot[j + 0]);
        int s1 = __ldg(&g_slot[j + 1]);
        int s2 = __ldg(&g_slot[j + 2]);
        int s3 = __ldg(&g_slot[j + 3]);
        float4 v0 = __ldg(&X4[(size_t)s0 * 32 + lane]);
        float4 v1 = __ldg(&X4[(size_t)s1 * 32 + lane]);
        float4 v2 = __ldg(&X4[(size_t)s2 * 32 + lane]);
        float4 v3 = __ldg(&X4[(size_t)s3 * 32 + lane]);
        a.x += v0.x + v1.x + v2.x + v3.x;
        a.y += v0.y + v1.y + v2.y + v3.y;
        a.z += v0.z + v1.z + v2.z + v3.z;
        a.w += v0.w + v1.w + v2.w + v3.w;
    }
    for (; j < e; j++) {
        int src = __ldg(&g_slot[j]);
        float4 v = __ldg(&X4[(size_t)src * 32 + lane]);
        a.x += v.x; a.y += v.y; a.z += v.z; a.w += v.w;
    }
    unsigned long long hp, lp;
    split4(a, hp, lp);
    Phi[(size_t)node * 32 + lane] = hp;
    Plo[(size_t)node * 32 + lane] = lp;
}

// ---------------- W prep: blocks 0-39 conv weights, 40-47 head weight ----------------
__global__ void prep_w_kernel(const float* W0, const float* W1, const float* W2,
                              const float* W3, const float* W4, const float* W5) {
    if (blockIdx.x >= 40) {
        int chunk = blockIdx.x - 40;
#pragma unroll
        for (int i = 0; i < 4; i++) {
            int idx = chunk * 1024 + i * 256 + threadIdx.x;
            int k = idx >> 6;
            int n = idx & 63;
            float w = (n < DOUT) ? __ldg(&W5[k * DOUT + n]) : 0.f;
            __nv_bfloat16 h = __float2bfloat16(w);
            __nv_bfloat16 l = __float2bfloat16(w - __bfloat162float(h));
            g_Wl2bf[0][k * HLD + n] = h;
            g_Wl2bf[1][k * HLD + n] = l;
        }
        return;
    }
    const float* Ws[5] = {W0, W1, W2, W3, W4};
    int p = blockIdx.x >> 3;
    int chunk = blockIdx.x & 7;
    const float* W = Ws[p];
    __nv_bfloat16* hi = g_Wbf[p][0];
    __nv_bfloat16* lo = g_Wbf[p][1];
#pragma unroll
    for (int i = 0; i < 8; i++) {
        int idx = chunk * 2048 + i * 256 + threadIdx.x;
        int k = idx >> 7;
        int n = idx & 127;
        float w = __ldg(&W[idx]);
        __nv_bfloat16 h = __float2bfloat16(w);
        __nv_bfloat16 l = __float2bfloat16(w - __bfloat162float(h));
        hi[k * WLD + n] = h;
        lo[k * WLD + n] = l;
    }
}

// ---------------- tensor-core GEMM (wmma bf16 hi/lo 3-term, fp32 accum) --------------
// 256 threads, 128 rows/CTA (proven R13 geometry). W via cp.async.
// PRESPLIT: A tiles are pre-split bf16 planes -> pure cp.async, no convert phase.
// BN_IN:    fp32 input; scale/shift+relu applied during convert.
// SPLIT_OUT: epilogue writes bf16 hi/lo planes (for next PRESPLIT consumer).
static const int GSM_TOTAL = 1536 + 4 * 128 * WLD * 2;   // 140800

template <bool RELU, bool STATS, bool BN_IN, bool PRESPLIT, bool SPLIT_OUT>
__global__ void __launch_bounds__(256) gemm_wmma_kernel(
    const float* __restrict__ Xf,                  // fp32 input (if !PRESPLIT)
    const __nv_bfloat16* __restrict__ Xhi,         // plane input (if PRESPLIT)
    const __nv_bfloat16* __restrict__ Xlo,
    const __nv_bfloat16* __restrict__ Whi,
    const __nv_bfloat16* __restrict__ Wlo,
    const float* __restrict__ Bias,
    const float* __restrict__ Gamma,
    const float* __restrict__ Beta,
    float* __restrict__ Yf,                        // fp32 output (if !SPLIT_OUT)
    unsigned long long* __restrict__ Yhi,          // plane output (if SPLIT_OUT)
    unsigned long long* __restrict__ Ylo,
    int nrows)
{
    extern __shared__ char smem[];
    float* sbias  = (float*)smem;
    float* sscale = (float*)(smem + 512);
    float* sshift = (float*)(smem + 1024);
    __nv_bfloat16* Ahi = (__nv_bfloat16*)(smem + 1536);
    __nv_bfloat16* Alo = Ahi + 128 * WLD;
    __nv_bfloat16* Bhi = Alo + 128 * WLD;
    __nv_bfloat16* Blo = Bhi + 128 * WLD;
    float* sout = (float*)(smem + 1536);   // reused after MMA (128x132 floats)

    int tid  = threadIdx.x;
    int row0 = blockIdx.x * 128;

    // W hi/lo tiles via cp.async
    {
        const uint4* sh = (const uint4*)Whi;
        const uint4* sl = (const uint4*)Wlo;
        uint4* dh = (uint4*)Bhi;
        uint4* dl = (uint4*)Blo;
#pragma unroll
        for (int i = 0; i < 9; i++) {
            int j = tid + i * 256;
            if (j < 2176) {
                cp_async16(&dh[j], &sh[j]);
                cp_async16(&dl[j], &sl[j]);
            }
        }
    }

    // A tiles: PRESPLIT -> cp.async straight from planes (row = 256B = 16 chunks)
    if (PRESPLIT) {
        const char* srcHi = (const char*)Xhi;
        const char* srcLo = (const char*)Xlo;
        char* dH = (char*)Ahi;
        char* dL = (char*)Alo;
#pragma unroll
        for (int i = 0; i < 8; i++) {
            int idx = tid + i * 256;          // 2048 chunks per plane
            int r = idx >> 4;
            int c = (idx & 15) * 16;
            size_t goff = (size_t)(row0 + r) * 256 + c;
            int soff = r * (WLD * 2) + c;
            cp_async16(dH + soff, srcHi + goff);
            cp_async16(dL + soff, srcLo + goff);
        }
    }
    cp_async_commit();

    if (tid < 128) {
        sbias[tid] = __ldg(&Bias[tid]);
        if (BN_IN) {
            const float invN = 1.0f / (float)NN;
            float mu  = g_sum[tid] * invN;
            float var = g_sqsum[tid] * invN - mu * mu;
            float rs  = rsqrtf(var + 1e-5f);
            float sc  = rs * __ldg(&Gamma[tid]);
            sscale[tid] = sc;
            sshift[tid] = __ldg(&Beta[tid]) - mu * sc;
        }
    }
    if (BN_IN) __syncthreads();

    // convert phase only for fp32 inputs
    if (!PRESPLIT) {
        const float4* X4 = (const float4*)Xf;
        int c4 = tid & 31;
        float4 sc, sh4;
        if (BN_IN) {
            sc  = ((const float4*)sscale)[c4];
            sh4 = ((const float4*)sshift)[c4];
        }
#pragma unroll
        for (int i = 0; i < 16; i++) {
            int idx = tid + i * 256;
            int r  = idx >> 5;
            int grow = row0 + r;
            float4 v = make_float4(0.f, 0.f, 0.f, 0.f);
            if (grow < nrows) v = __ldg(&X4[(size_t)grow * 32 + c4]);
            if (BN_IN) {
                v.x = fmaxf(v.x * sc.x + sh4.x, 0.f);
                v.y = fmaxf(v.y * sc.y + sh4.y, 0.f);
                v.z = fmaxf(v.z * sc.z + sh4.z, 0.f);
                v.w = fmaxf(v.w * sc.w + sh4.w, 0.f);
            }
            unsigned long long hp, lp;
            split4(v, hp, lp);
            *(unsigned long long*)((char*)Ahi + r * (WLD * 2) + c4 * 8) = hp;
            *(unsigned long long*)((char*)Alo + r * (WLD * 2) + c4 * 8) = lp;
        }
    }
    cp_async_wait_all();
    __syncthreads();

    // MMA: warp w -> rows (w&3)*32..+32, cols (w>>2)*64..+64
    int w  = tid >> 5;
    int wr = (w & 3) * 32;
    int wc = (w >> 2) * 64;

    wmma::fragment<wmma::accumulator, 16, 16, 16, float> acc[2][4];
#pragma unroll
    for (int i = 0; i < 2; i++)
#pragma unroll
        for (int j = 0; j < 4; j++) wmma::fill_fragment(acc[i][j], 0.f);

#pragma unroll
    for (int k = 0; k < 8; k++) {
        wmma::fragment<wmma::matrix_a, 16, 16, 16, __nv_bfloat16, wmma::row_major> ah[2], al[2];
        wmma::fragment<wmma::matrix_b, 16, 16, 16, __nv_bfloat16, wmma::row_major> bh[4], bl[4];
#pragma unroll
        for (int i = 0; i < 2; i++) {
            wmma::load_matrix_sync(ah[i], Ahi + (wr + 16 * i) * WLD + k * 16, WLD);
            wmma::load_matrix_sync(al[i], Alo + (wr + 16 * i) * WLD + k * 16, WLD);
        }
#pragma unroll
        for (int j = 0; j < 4; j++) {
            wmma::load_matrix_sync(bh[j], Bhi + (k * 16) * WLD + wc + 16 * j, WLD);
            wmma::load_matrix_sync(bl[j], Blo + (k * 16) * WLD + wc + 16 * j, WLD);
        }
#pragma unroll
        for (int i = 0; i < 2; i++)
#pragma unroll
            for (int j = 0; j < 4; j++) {
                wmma::mma_sync(acc[i][j], ah[i], bh[j], acc[i][j]);
                wmma::mma_sync(acc[i][j], ah[i], bl[j], acc[i][j]);
                wmma::mma_sync(acc[i][j], al[i], bh[j], acc[i][j]);
            }
    }
    __syncthreads();

#pragma unroll
    for (int i = 0; i < 2; i++)
#pragma unroll
        for (int j = 0; j < 4; j++)
            wmma::store_matrix_sync(sout + (wr + 16 * i) * 132 + wc + 16 * j,
                                    acc[i][j], 132, wmma::mem_row_major);
    __syncthreads();

    // bias + relu + output write (+ column stats partials)
    float cs[4] = {0.f, 0.f, 0.f, 0.f};
    float cq[4] = {0.f, 0.f, 0.f, 0.f};
    {
        int c4 = tid & 31;
        float4 b = ((const float4*)sbias)[c4];
#pragma unroll
        for (int i = 0; i < 16; i++) {
            int idx = tid + i * 256;
            int r  = idx >> 5;
            int grow = row0 + r;
            if (grow >= nrows) continue;
            float4 v = ((const float4*)(sout + r * 132))[c4];
            v.x += b.x; v.y += b.y; v.z += b.z; v.w += b.w;
            if (RELU) {
                v.x = fmaxf(v.x, 0.f); v.y = fmaxf(v.y, 0.f);
                v.z = fmaxf(v.z, 0.f); v.w = fmaxf(v.w, 0.f);
            }
            if (STATS) {
                cs[0] += v.x; cq[0] += v.x * v.x;
                cs[1] += v.y; cq[1] += v.y * v.y;
                cs[2] += v.z; cq[2] += v.z * v.z;
                cs[3] += v.w; cq[3] += v.w * v.w;
            }
            if (SPLIT_OUT) {
                unsigned long long hp, lp;
                split4(v, hp, lp);
                Yhi[(size_t)grow * 32 + c4] = hp;
                Ylo[(size_t)grow * 32 + c4] = lp;
            } else {
                ((float4*)Yf)[(size_t)grow * 32 + c4] = v;
            }
        }
    }

    if (STATS) {
        __syncthreads();
        float* ssum = sout;
        float* ssq  = sout + 1024;
        int g  = tid >> 5;
        int c4 = tid & 31;
#pragma unroll
        for (int j = 0; j < 4; j++) {
            ssum[g * 128 + c4 * 4 + j] = cs[j];
            ssq[g * 128 + c4 * 4 + j]  = cq[j];
        }
        __syncthreads();
        if (tid < 128) {
            float a = 0.f;
#pragma unroll
            for (int gg = 0; gg < 8; gg++) a += ssum[gg * 128 + tid];
            atomicAdd(&g_sum[tid], a);
        } else {
            int c = tid - 128;
            float a = 0.f;
#pragma unroll
            for (int gg = 0; gg < 8; gg++) a += ssq[gg * 128 + c];
            atomicAdd(&g_sqsum[c], a);
        }
    }
}

// ---------------- tensor-core head: logits + fused log-softmax (PRESPLIT input) -------
static const int HSM_TOTAL = 256 + 2 * (128 * WLD * 2) + 2 * (128 * HLD * 2);

__global__ void __launch_bounds__(256) head_wmma_kernel(
    const __nv_bfloat16* __restrict__ Xhi,
    const __nv_bfloat16* __restrict__ Xlo,
    const float* __restrict__ Bias,
    float* __restrict__ out, int nrows)
{
    extern __shared__ char smem[];
    float* sbias = (float*)smem;
    __nv_bfloat16* Ahi = (__nv_bfloat16*)(smem + 256);
    __nv_bfloat16* Alo = Ahi + 128 * WLD;
    __nv_bfloat16* Bhi = Alo + 128 * WLD;
    __nv_bfloat16* Blo = Bhi + 128 * HLD;
    float* sout = (float*)(smem + 256);

    int tid  = threadIdx.x;
    int row0 = blockIdx.x * 128;

    // B tiles via cp.async: 128*72 bf16 = 1152 uint4 each
    {
        const uint4* sh = (const uint4*)&g_Wl2bf[0][0];
        const uint4* sl = (const uint4*)&g_Wl2bf[1][0];
        uint4* dh = (uint4*)Bhi;
        uint4* dl = (uint4*)Blo;
#pragma unroll
        for (int i = 0; i < 5; i++) {
            int j = tid + i * 256;
            if (j < 1152) {
                cp_async16(&dh[j], &sh[j]);
                cp_async16(&dl[j], &sl[j]);
            }
        }
    }
    // A tiles via cp.async from planes
    {
        const char* srcHi = (const char*)Xhi;
        const char* srcLo = (const char*)Xlo;
        char* dH = (char*)Ahi;
        char* dL = (char*)Alo;
#pragma unroll
        for (int i = 0; i < 8; i++) {
            int idx = tid + i * 256;
            int r = idx >> 4;
            int c = (idx & 15) * 16;
            size_t goff = (size_t)(row0 + r) * 256 + c;
            int soff = r * (WLD * 2) + c;
            cp_async16(dH + soff, srcHi + goff);
            cp_async16(dL + soff, srcLo + goff);
        }
    }
    cp_async_commit();
    if (tid < 64) sbias[tid] = (tid < DOUT) ? __ldg(&Bias[tid]) : 0.f;
    cp_async_wait_all();
    __syncthreads();

    int w  = tid >> 5;
    int wr = w * 16;

    wmma::fragment<wmma::accumulator, 16, 16, 16, float> acc[4];
#pragma unroll
    for (int j = 0; j < 4; j++) wmma::fill_fragment(acc[j], 0.f);

#pragma unroll
    for (int k = 0; k < 8; k++) {
        wmma::fragment<wmma::matrix_a, 16, 16, 16, __nv_bfloat16, wmma::row_major> ah, al;
        wmma::fragment<wmma::matrix_b, 16, 16, 16, __nv_bfloat16, wmma::row_major> bh[4], bl[4];
        wmma::load_matrix_sync(ah, Ahi + wr * WLD + k * 16, WLD);
        wmma::load_matrix_sync(al, Alo + wr * WLD + k * 16, WLD);
#pragma unroll
        for (int j = 0; j < 4; j++) {
            wmma::load_matrix_sync(bh[j], Bhi + (k * 16) * HLD + 16 * j, HLD);
            wmma::load_matrix_sync(bl[j], Blo + (k * 16) * HLD + 16 * j, HLD);
        }
#pragma unroll
        for (int j = 0; j < 4; j++) {
            wmma::mma_sync(acc[j], ah, bh[j], acc[j]);
            wmma::mma_sync(acc[j], ah, bl[j], acc[j]);
            wmma::mma_sync(acc[j], al, bh[j], acc[j]);
        }
    }
    __syncthreads();

#pragma unroll
    for (int j = 0; j < 4; j++)
        wmma::store_matrix_sync(sout + wr * HLD + 16 * j, acc[j], HLD,
                                wmma::mem_row_major);
    __syncthreads();

    if (tid < 128) {
        int grow = row0 + tid;
        if (grow < nrows) {
            const float* l = sout + tid * HLD;
            float v[DOUT];
#pragma unroll
            for (int j = 0; j < DOUT; j++) v[j] = l[j] + sbias[j];
            float m = v[0];
#pragma unroll
            for (int j = 1; j < DOUT; j++) m = fmaxf(m, v[j]);
            float s = 0.f;
#pragma unroll
            for (int j = 0; j < DOUT; j++) s += expf(v[j] - m);
            float lse = logf(s) + m;
            float4* o4 = (float4*)(out + (size_t)grow * DOUT);
#pragma unroll
            for (int i = 0; i < 10; i++) {
                float4 o;
                o.x = v[i*4+0] - lse; o.y = v[i*4+1] - lse;
                o.z = v[i*4+2] - lse; o.w = v[i*4+3] - lse;
                o4[i] = o;
            }
        }
    }
}

// ---------------- host launch ----------------
extern "C" void kernel_launch(void* const* d_in, const int* in_sizes, int n_in,
                              void* d_out, int out_size) {
    const float* x   = (const float*)d_in[0];
    const int*   ei  = (const int*)d_in[1];
    const float* W1a = (const float*)d_in[2];
    const float* b1a = (const float*)d_in[3];
    const float* g1  = (const float*)d_in[4];
    const float* be1 = (const float*)d_in[5];
    const float* W2a = (const float*)d_in[6];
    const float* b2a = (const float*)d_in[7];
    const float* W1b = (const float*)d_in[8];
    const float* b1b = (const float*)d_in[9];
    const float* g2  = (const float*)d_in[10];
    const float* be2 = (const float*)d_in[11];
    const float* W2b = (const float*)d_in[12];
    const float* b2b = (const float*)d_in[13];
    const float* Wl1 = (const float*)d_in[14];
    const float* bl1 = (const float*)d_in[15];
    const float* Wl2 = (const float*)d_in[16];
    const float* bl2 = (const float*)d_in[17];
    float* out = (float*)d_out;

    float *pB, *pC;
    cudaGetSymbolAddress((void**)&pB, g_bufB);
    cudaGetSymbolAddress((void**)&pC, g_bufC);
    __nv_bfloat16* pl;
    cudaGetSymbolAddress((void**)&pl, g_pl);
    __nv_bfloat16* wt;
    cudaGetSymbolAddress((void**)&wt, g_Wbf);
    int* pDeg;
    cudaGetSymbolAddress((void**)&pDeg, g_deg);

    // plane pointers: set s, hi/lo
    const size_t plsz = (size_t)NPAD * DH;
    __nv_bfloat16* P0h = pl;
    __nv_bfloat16* P0l = pl + plsz;
    __nv_bfloat16* P1h = pl + 2 * plsz;
    __nv_bfloat16* P1l = pl + 3 * plsz;

    cudaFuncSetAttribute((const void*)gemm_wmma_kernel<false, true, false, true, false>,
                         cudaFuncAttributeMaxDynamicSharedMemorySize, GSM_TOTAL);
    cudaFuncSetAttribute((const void*)gemm_wmma_kernel<true, false, true, false, false>,
                         cudaFuncAttributeMaxDynamicSharedMemorySize, GSM_TOTAL);
    cudaFuncSetAttribute((const void*)gemm_wmma_kernel<true, false, true, false, true>,
                         cudaFuncAttributeMaxDynamicSharedMemorySize, GSM_TOTAL);
    cudaFuncSetAttribute((const void*)gemm_wmma_kernel<true, false, false, true, true>,
                         cudaFuncAttributeMaxDynamicSharedMemorySize, GSM_TOTAL);
    cudaFuncSetAttribute((const void*)head_wmma_kernel,
                         cudaFuncAttributeMaxDynamicSharedMemorySize, HSM_TOTAL);

    const int edgeGrid = (EE + 255) / 256;
    const int aggGrid  = (NN + 7) / 8;
    const int tcGrid   = (NN + 127) / 128;
    const size_t wpage = (size_t)128 * WLD;

    prep_w_kernel<<<48, 256>>>(W1a, W2a, W1b, W2b, Wl1, Wl2);
    cudaMemsetAsync(pDeg, 0, NN * sizeof(int));
    hist_kernel<<<edgeGrid, 256>>>(ei);
    scan_kernel<<<1, 1024>>>();
    fill_kernel<<<edgeGrid, 256>>>(ei);
#define WHI(p) (wt + (size_t)(p) * 2 * wpage)
#define WLO(p) (wt + (size_t)(p) * 2 * wpage + wpage)

    // ---- conv1 ----
    aggregate_kernel<<<aggGrid, 256>>>(x, (unsigned long long*)P0h, (unsigned long long*)P0l);
    gemm_wmma_kernel<false, true, false, true, false><<<tcGrid, 256, GSM_TOTAL>>>(
        nullptr, P0h, P0l, WHI(0), WLO(0), b1a, nullptr, nullptr,
        pB, nullptr, nullptr, NN);
    gemm_wmma_kernel<true, false, true, false, false><<<tcGrid, 256, GSM_TOTAL>>>(
        pB, nullptr, nullptr, WHI(1), WLO(1), b2a, g1, be1,
        pC, nullptr, nullptr, NN);

    // ---- conv2 ----
    aggregate_kernel<<<aggGrid, 256>>>(pC, (unsigned long long*)P0h, (unsigned long long*)P0l);
    gemm_wmma_kernel<false, true, false, true, false><<<tcGrid, 256, GSM_TOTAL>>>(
        nullptr, P0h, P0l, WHI(2), WLO(2), b1b, nullptr, nullptr,
        pB, nullptr, nullptr, NN);
    gemm_wmma_kernel<true, false, true, false, true><<<tcGrid, 256, GSM_TOTAL>>>(
        pB, nullptr, nullptr, WHI(3), WLO(3), b2b, g2, be2,
        nullptr, (unsigned long long*)P1h, (unsigned long long*)P1l, NN);

    // ---- head ----
    gemm_wmma_kernel<true, false, false, true, true><<<tcGrid, 256, GSM_TOTAL>>>(
        nullptr, P1h, P1l, WHI(4), WLO(4), bl1, nullptr, nullptr,
        nullptr, (unsigned long long*)P0h, (unsigned long long*)P0l, NN);
    head_wmma_kernel<<<tcGrid, 256, HSM_TOTAL>>>(P0h, P0l, bl2, out, NN);
}

// round 17
// speedup vs baseline: 1.0069x; 1.0069x over previous
#include <cuda_runtime.h>
#include <cuda_bf16.h>
#include <mma.h>
#include <math.h>
#include <stdint.h>

using namespace nvcuda;

#define NN 50000
#define EE 800000
#define DH 128
#define DOUT 40
#define WLD 136   // padded leading dim for bf16 tiles
#define HLD 72    // padded leading dim for head B tile

// ---------------- scratch (device globals; no allocation allowed) ----------------
__device__ float g_bufA[NN * DH];
__device__ float g_bufB[NN * DH];
__device__ float g_bufC[NN * DH];
__device__ float g_sum[DH];
__device__ float g_sqsum[DH];
__device__ int   g_deg[NN];
__device__ int   g_off[NN + 1];
__device__ int   g_rank[EE];
__device__ int   g_slot[EE];
__device__ __nv_bfloat16 g_Wbf[5][2][128 * WLD];
__device__ __nv_bfloat16 g_Wl2bf[2][128 * HLD];

// ---------------- helpers ----------------
__device__ __forceinline__ unsigned short bfu(float v) {
    __nv_bfloat16 h = __float2bfloat16(v);
    return *reinterpret_cast<unsigned short*>(&h);
}
__device__ __forceinline__ float bff(unsigned short u) {
    __nv_bfloat16 h = *reinterpret_cast<__nv_bfloat16*>(&u);
    return __bfloat162float(h);
}
__device__ __forceinline__ void split4(float4 v, unsigned long long& hp, unsigned long long& lp) {
    unsigned short h0 = bfu(v.x), h1 = bfu(v.y), h2 = bfu(v.z), h3 = bfu(v.w);
    unsigned short l0 = bfu(v.x - bff(h0)), l1 = bfu(v.y - bff(h1));
    unsigned short l2 = bfu(v.z - bff(h2)), l3 = bfu(v.w - bff(h3));
    hp = (unsigned long long)h0 | ((unsigned long long)h1 << 16)
       | ((unsigned long long)h2 << 32) | ((unsigned long long)h3 << 48);
    lp = (unsigned long long)l0 | ((unsigned long long)l1 << 16)
       | ((unsigned long long)l2 << 32) | ((unsigned long long)l3 << 48);
}

__device__ __forceinline__ void cp_async16(void* smem_dst, const void* gmem_src) {
    uint32_t s = (uint32_t)__cvta_generic_to_shared(smem_dst);
    asm volatile("cp.async.cg.shared.global [%0], [%1], 16;" :: "r"(s), "l"(gmem_src));
}
__device__ __forceinline__ void cp_async_commit() {
    asm volatile("cp.async.commit_group;" ::: "memory");
}
__device__ __forceinline__ void cp_async_wait_all() {
    asm volatile("cp.async.wait_group 0;" ::: "memory");
}

// ---------------- CSR build ----------------
__global__ void hist_kernel(const int* __restrict__ ei) {
    int e = blockIdx.x * blockDim.x + threadIdx.x;
    if (e >= EE) return;
    int dst = min(max(__ldg(&ei[EE + e]), 0), NN - 1);
    g_rank[e] = atomicAdd(&g_deg[dst], 1);
}

__global__ void __launch_bounds__(1024) scan_kernel() {
    const int CH = (NN + 1023) / 1024;
    int t = threadIdx.x;
    int base = t * CH;
    int s = 0;
    for (int i = 0; i < CH; i++) {
        int idx = base + i;
        if (idx < NN) s += g_deg[idx];
    }
    __shared__ int sh[1024];
    sh[t] = s;
    __syncthreads();
    for (int off = 1; off < 1024; off <<= 1) {
        int v = (t >= off) ? sh[t - off] : 0;
        __syncthreads();
        sh[t] += v;
        __syncthreads();
    }
    int run = sh[t] - s;
    for (int i = 0; i < CH; i++) {
        int idx = base + i;
        if (idx < NN) {
            g_off[idx] = run;
            run += g_deg[idx];
        }
    }
    if (t == 1023) g_off[NN] = run;
}

__global__ void fill_kernel(const int* __restrict__ ei) {
    int e = blockIdx.x * blockDim.x + threadIdx.x;
    if (e >= EE) return;
    int src = min(max(__ldg(&ei[e]), 0), NN - 1);
    int dst = min(max(__ldg(&ei[EE + e]), 0), NN - 1);
    int pos = __ldg(&g_off[dst]) + g_rank[e];
    g_slot[pos] = src;
}

// ---------------- aggregation: warp per node, 8-wide edge unroll ----------------
// block 0 also zeroes the BN stats accumulators.
__global__ void __launch_bounds__(256) aggregate_kernel(const float* __restrict__ X,
                                                        float* __restrict__ agg) {
    if (blockIdx.x == 0 && threadIdx.x < 128) {
        g_sum[threadIdx.x] = 0.f;
        g_sqsum[threadIdx.x] = 0.f;
    }
    int node = blockIdx.x * 8 + (threadIdx.x >> 5);
    if (node >= NN) return;
    int lane = threadIdx.x & 31;
    const float4* X4 = (const float4*)X;
    float4 a = __ldg(&X4[(size_t)node * 32 + lane]);
    int s = __ldg(&g_off[node]);
    int e = __ldg(&g_off[node + 1]);
    int j = s;
    for (; j + 8 <= e; j += 8) {
        int si[8];
#pragma unroll
        for (int q = 0; q < 8; q++) si[q] = __ldg(&g_slot[j + q]);
        float4 v[8];
#pragma unroll
        for (int q = 0; q < 8; q++) v[q] = __ldg(&X4[(size_t)si[q] * 32 + lane]);
#pragma unroll
        for (int q = 0; q < 8; q++) {
            a.x += v[q].x; a.y += v[q].y; a.z += v[q].z; a.w += v[q].w;
        }
    }
    for (; j < e; j++) {
        int src = __ldg(&g_slot[j]);
        float4 v = __ldg(&X4[(size_t)src * 32 + lane]);
        a.x += v.x; a.y += v.y; a.z += v.z; a.w += v.w;
    }
    ((float4*)agg)[(size_t)node * 32 + lane] = a;
}

// ---------------- W prep: 0-39 conv W, 40-47 head W, 48-49 zero g_deg ---------------
__global__ void prep_w_kernel(const float* W0, const float* W1, const float* W2,
                              const float* W3, const float* W4, const float* W5) {
    if (blockIdx.x >= 48) {
        // zero g_deg: 50000 ints over 2 blocks x 256 threads
        int base = (blockIdx.x - 48) * 25088 + threadIdx.x;
        for (int i = 0; i < 98; i++) {
            int idx = base + i * 256;
            if (idx < NN) g_deg[idx] = 0;
        }
        return;
    }
    if (blockIdx.x >= 40) {
        int chunk = blockIdx.x - 40;
#pragma unroll
        for (int i = 0; i < 4; i++) {
            int idx = chunk * 1024 + i * 256 + threadIdx.x;
            int k = idx >> 6;
            int n = idx & 63;
            float w = (n < DOUT) ? __ldg(&W5[k * DOUT + n]) : 0.f;
            __nv_bfloat16 h = __float2bfloat16(w);
            __nv_bfloat16 l = __float2bfloat16(w - __bfloat162float(h));
            g_Wl2bf[0][k * HLD + n] = h;
            g_Wl2bf[1][k * HLD + n] = l;
        }
        return;
    }
    const float* Ws[5] = {W0, W1, W2, W3, W4};
    int p = blockIdx.x >> 3;
    int chunk = blockIdx.x & 7;
    const float* W = Ws[p];
    __nv_bfloat16* hi = g_Wbf[p][0];
    __nv_bfloat16* lo = g_Wbf[p][1];
#pragma unroll
    for (int i = 0; i < 8; i++) {
        int idx = chunk * 2048 + i * 256 + threadIdx.x;
        int k = idx >> 7;
        int n = idx & 127;
        float w = __ldg(&W[idx]);
        __nv_bfloat16 h = __float2bfloat16(w);
        __nv_bfloat16 l = __float2bfloat16(w - __bfloat162float(h));
        hi[k * WLD + n] = h;
        lo[k * WLD + n] = l;
    }
}

// ---------------- tensor-core GEMM (wmma bf16 hi/lo 3-term, fp32 accum) --------------
// 256 threads, 128 rows/CTA (proven geometry). W via cp.async overlapped with convert.
static const int GSM_TOTAL = 1536 + 4 * 128 * WLD * 2;   // 140800

template <bool RELU, bool STATS, bool BN_IN>
__global__ void __launch_bounds__(256) gemm_wmma_kernel(
    const float* __restrict__ X,
    const __nv_bfloat16* __restrict__ Whi,
    const __nv_bfloat16* __restrict__ Wlo,
    const float* __restrict__ Bias,
    const float* __restrict__ Gamma,
    const float* __restrict__ Beta,
    float* __restrict__ Y, int nrows)
{
    extern __shared__ char smem[];
    float* sbias  = (float*)smem;
    float* sscale = (float*)(smem + 512);
    float* sshift = (float*)(smem + 1024);
    __nv_bfloat16* Ahi = (__nv_bfloat16*)(smem + 1536);
    __nv_bfloat16* Alo = Ahi + 128 * WLD;
    __nv_bfloat16* Bhi = Alo + 128 * WLD;
    __nv_bfloat16* Blo = Bhi + 128 * WLD;
    float* sout = (float*)(smem + 1536);   // reused after MMA (128x132 floats)

    int tid  = threadIdx.x;
    int row0 = blockIdx.x * 128;

    // W hi/lo tiles via cp.async (completes during X convert)
    {
        const uint4* sh = (const uint4*)Whi;
        const uint4* sl = (const uint4*)Wlo;
        uint4* dh = (uint4*)Bhi;
        uint4* dl = (uint4*)Blo;
#pragma unroll
        for (int i = 0; i < 9; i++) {
            int j = tid + i * 256;
            if (j < 2176) {
                cp_async16(&dh[j], &sh[j]);
                cp_async16(&dl[j], &sl[j]);
            }
        }
        cp_async_commit();
    }

    if (tid < 128) {
        sbias[tid] = __ldg(&Bias[tid]);
        if (BN_IN) {
            const float invN = 1.0f / (float)NN;
            float mu  = g_sum[tid] * invN;
            float var = g_sqsum[tid] * invN - mu * mu;
            float rs  = rsqrtf(var + 1e-5f);
            float sc  = rs * __ldg(&Gamma[tid]);
            sscale[tid] = sc;
            sshift[tid] = __ldg(&Beta[tid]) - mu * sc;
        }
    }
    if (BN_IN) __syncthreads();

    // X tile -> bf16 hi/lo (packed u64 stores; optional BN+relu on the fly)
    {
        const float4* X4 = (const float4*)X;
        int c4 = tid & 31;
        float4 sc, sh4;
        if (BN_IN) {
            sc  = ((const float4*)sscale)[c4];
            sh4 = ((const float4*)sshift)[c4];
        }
#pragma unroll
        for (int i = 0; i < 16; i++) {
            int idx = tid + i * 256;
            int r  = idx >> 5;
            int grow = row0 + r;
            float4 v = make_float4(0.f, 0.f, 0.f, 0.f);
            if (grow < nrows) v = __ldg(&X4[(size_t)grow * 32 + c4]);
            if (BN_IN) {
                v.x = fmaxf(v.x * sc.x + sh4.x, 0.f);
                v.y = fmaxf(v.y * sc.y + sh4.y, 0.f);
                v.z = fmaxf(v.z * sc.z + sh4.z, 0.f);
                v.w = fmaxf(v.w * sc.w + sh4.w, 0.f);
            }
            unsigned long long hp, lp;
            split4(v, hp, lp);
            *(unsigned long long*)((char*)Ahi + r * (WLD * 2) + c4 * 8) = hp;
            *(unsigned long long*)((char*)Alo + r * (WLD * 2) + c4 * 8) = lp;
        }
    }
    cp_async_wait_all();
    __syncthreads();

    // MMA: warp w -> rows (w&3)*32..+32, cols (w>>2)*64..+64
    int w  = tid >> 5;
    int wr = (w & 3) * 32;
    int wc = (w >> 2) * 64;

    wmma::fragment<wmma::accumulator, 16, 16, 16, float> acc[2][4];
#pragma unroll
    for (int i = 0; i < 2; i++)
#pragma unroll
        for (int j = 0; j < 4; j++) wmma::fill_fragment(acc[i][j], 0.f);

#pragma unroll
    for (int k = 0; k < 8; k++) {
        wmma::fragment<wmma::matrix_a, 16, 16, 16, __nv_bfloat16, wmma::row_major> ah[2], al[2];
        wmma::fragment<wmma::matrix_b, 16, 16, 16, __nv_bfloat16, wmma::row_major> bh[4], bl[4];
#pragma unroll
        for (int i = 0; i < 2; i++) {
            wmma::load_matrix_sync(ah[i], Ahi + (wr + 16 * i) * WLD + k * 16, WLD);
            wmma::load_matrix_sync(al[i], Alo + (wr + 16 * i) * WLD + k * 16, WLD);
        }
#pragma unroll
        for (int j = 0; j < 4; j++) {
            wmma::load_matrix_sync(bh[j], Bhi + (k * 16) * WLD + wc + 16 * j, WLD);
            wmma::load_matrix_sync(bl[j], Blo + (k * 16) * WLD + wc + 16 * j, WLD);
        }
#pragma unroll
        for (int i = 0; i < 2; i++)
#pragma unroll
            for (int j = 0; j < 4; j++) {
                wmma::mma_sync(acc[i][j], ah[i], bh[j], acc[i][j]);
                wmma::mma_sync(acc[i][j], ah[i], bl[j], acc[i][j]);
                wmma::mma_sync(acc[i][j], al[i], bh[j], acc[i][j]);
            }
    }
    __syncthreads();

#pragma unroll
    for (int i = 0; i < 2; i++)
#pragma unroll
        for (int j = 0; j < 4; j++)
            wmma::store_matrix_sync(sout + (wr + 16 * i) * 132 + wc + 16 * j,
                                    acc[i][j], 132, wmma::mem_row_major);
    __syncthreads();

    // bias + relu + global write (+ column stats partials)
    float cs[4] = {0.f, 0.f, 0.f, 0.f};
    float cq[4] = {0.f, 0.f, 0.f, 0.f};
    {
        float4* Y4 = (float4*)Y;
        int c4 = tid & 31;
        float4 b = ((const float4*)sbias)[c4];
#pragma unroll
        for (int i = 0; i < 16; i++) {
            int idx = tid + i * 256;
            int r  = idx >> 5;
            int grow = row0 + r;
            if (grow >= nrows) continue;
            float4 v = ((const float4*)(sout + r * 132))[c4];
            v.x += b.x; v.y += b.y; v.z += b.z; v.w += b.w;
            if (RELU) {
                v.x = fmaxf(v.x, 0.f); v.y = fmaxf(v.y, 0.f);
                v.z = fmaxf(v.z, 0.f); v.w = fmaxf(v.w, 0.f);
            }
            if (STATS) {
                cs[0] += v.x; cq[0] += v.x * v.x;
                cs[1] += v.y; cq[1] += v.y * v.y;
                cs[2] += v.z; cq[2] += v.z * v.z;
                cs[3] += v.w; cq[3] += v.w * v.w;
            }
            Y4[(size_t)grow * 32 + c4] = v;
        }
    }

    if (STATS) {
        __syncthreads();
        float* ssum = sout;
        float* ssq  = sout + 1024;
        int g  = tid >> 5;
        int c4 = tid & 31;
#pragma unroll
        for (int j = 0; j < 4; j++) {
            ssum[g * 128 + c4 * 4 + j] = cs[j];
            ssq[g * 128 + c4 * 4 + j]  = cq[j];
        }
        __syncthreads();
        if (tid < 128) {
            float a = 0.f;
#pragma unroll
            for (int gg = 0; gg < 8; gg++) a += ssum[gg * 128 + tid];
            atomicAdd(&g_sum[tid], a);
        } else {
            int c = tid - 128;
            float a = 0.f;
#pragma unroll
            for (int gg = 0; gg < 8; gg++) a += ssq[gg * 128 + c];
            atomicAdd(&g_sqsum[c], a);
        }
    }
}

// ---------------- tensor-core head: logits + fused log-softmax ----------------------
static const int HSM_TOTAL = 256 + 2 * (128 * WLD * 2) + 2 * (128 * HLD * 2);

__global__ void __launch_bounds__(256) head_wmma_kernel(
    const float* __restrict__ X,
    const float* __restrict__ Bias,
    float* __restrict__ out, int nrows)
{
    extern __shared__ char smem[];
    float* sbias = (float*)smem;
    __nv_bfloat16* Ahi = (__nv_bfloat16*)(smem + 256);
    __nv_bfloat16* Alo = Ahi + 128 * WLD;
    __nv_bfloat16* Bhi = Alo + 128 * WLD;
    __nv_bfloat16* Blo = Bhi + 128 * HLD;
    float* sout = (float*)(smem + 256);

    int tid  = threadIdx.x;
    int row0 = blockIdx.x * 128;

    {
        const uint4* sh = (const uint4*)&g_Wl2bf[0][0];
        const uint4* sl = (const uint4*)&g_Wl2bf[1][0];
        uint4* dh = (uint4*)Bhi;
        uint4* dl = (uint4*)Blo;
#pragma unroll
        for (int i = 0; i < 5; i++) {
            int j = tid + i * 256;
            if (j < 1152) {
                cp_async16(&dh[j], &sh[j]);
                cp_async16(&dl[j], &sl[j]);
            }
        }
        cp_async_commit();
    }
    if (tid < 64) sbias[tid] = (tid < DOUT) ? __ldg(&Bias[tid]) : 0.f;

    {
        const float4* X4 = (const float4*)X;
        int c4 = tid & 31;
#pragma unroll
        for (int i = 0; i < 16; i++) {
            int idx = tid + i * 256;
            int r  = idx >> 5;
            int grow = row0 + r;
            float4 v = make_float4(0.f, 0.f, 0.f, 0.f);
            if (grow < nrows) v = __ldg(&X4[(size_t)grow * 32 + c4]);
            unsigned long long hp, lp;
            split4(v, hp, lp);
            *(unsigned long long*)((char*)Ahi + r * (WLD * 2) + c4 * 8) = hp;
            *(unsigned long long*)((char*)Alo + r * (WLD * 2) + c4 * 8) = lp;
        }
    }
    cp_async_wait_all();
    __syncthreads();

    int w  = tid >> 5;
    int wr = w * 16;

    wmma::fragment<wmma::accumulator, 16, 16, 16, float> acc[4];
#pragma unroll
    for (int j = 0; j < 4; j++) wmma::fill_fragment(acc[j], 0.f);

#pragma unroll
    for (int k = 0; k < 8; k++) {
        wmma::fragment<wmma::matrix_a, 16, 16, 16, __nv_bfloat16, wmma::row_major> ah, al;
        wmma::fragment<wmma::matrix_b, 16, 16, 16, __nv_bfloat16, wmma::row_major> bh[4], bl[4];
        wmma::load_matrix_sync(ah, Ahi + wr * WLD + k * 16, WLD);
        wmma::load_matrix_sync(al, Alo + wr * WLD + k * 16, WLD);
#pragma unroll
        for (int j = 0; j < 4; j++) {
            wmma::load_matrix_sync(bh[j], Bhi + (k * 16) * HLD + 16 * j, HLD);
            wmma::load_matrix_sync(bl[j], Blo + (k * 16) * HLD + 16 * j, HLD);
        }
#pragma unroll
        for (int j = 0; j < 4; j++) {
            wmma::mma_sync(acc[j], ah, bh[j], acc[j]);
            wmma::mma_sync(acc[j], ah, bl[j], acc[j]);
            wmma::mma_sync(acc[j], al, bh[j], acc[j]);
        }
    }
    __syncthreads();

#pragma unroll
    for (int j = 0; j < 4; j++)
        wmma::store_matrix_sync(sout + wr * HLD + 16 * j, acc[j], HLD,
                                wmma::mem_row_major);
    __syncthreads();

    if (tid < 128) {
        int grow = row0 + tid;
        if (grow < nrows) {
            const float* l = sout + tid * HLD;
            float v[DOUT];
#pragma unroll
            for (int j = 0; j < DOUT; j++) v[j] = l[j] + sbias[j];
            float m = v[0];
#pragma unroll
            for (int j = 1; j < DOUT; j++) m = fmaxf(m, v[j]);
            float s = 0.f;
#pragma unroll
            for (int j = 0; j < DOUT; j++) s += expf(v[j] - m);
            float lse = logf(s) + m;
            float4* o4 = (float4*)(out + (size_t)grow * DOUT);
#pragma unroll
            for (int i = 0; i < 10; i++) {
                float4 o;
                o.x = v[i*4+0] - lse; o.y = v[i*4+1] - lse;
                o.z = v[i*4+2] - lse; o.w = v[i*4+3] - lse;
                o4[i] = o;
            }
        }
    }
}

// ---------------- host launch ----------------
extern "C" void kernel_launch(void* const* d_in, const int* in_sizes, int n_in,
                              void* d_out, int out_size) {
    const float* x   = (const float*)d_in[0];
    const int*   ei  = (const int*)d_in[1];
    const float* W1a = (const float*)d_in[2];
    const float* b1a = (const float*)d_in[3];
    const float* g1  = (const float*)d_in[4];
    const float* be1 = (const float*)d_in[5];
    const float* W2a = (const float*)d_in[6];
    const float* b2a = (const float*)d_in[7];
    const float* W1b = (const float*)d_in[8];
    const float* b1b = (const float*)d_in[9];
    const float* g2  = (const float*)d_in[10];
    const float* be2 = (const float*)d_in[11];
    const float* W2b = (const float*)d_in[12];
    const float* b2b = (const float*)d_in[13];
    const float* Wl1 = (const float*)d_in[14];
    const float* bl1 = (const float*)d_in[15];
    const float* Wl2 = (const float*)d_in[16];
    const float* bl2 = (const float*)d_in[17];
    float* out = (float*)d_out;

    float *pA, *pB, *pC;
    cudaGetSymbolAddress((void**)&pA, g_bufA);
    cudaGetSymbolAddress((void**)&pB, g_bufB);
    cudaGetSymbolAddress((void**)&pC, g_bufC);
    __nv_bfloat16* wt;
    cudaGetSymbolAddress((void**)&wt, g_Wbf);

    cudaFuncSetAttribute(gemm_wmma_kernel<false, true,  false>, cudaFuncAttributeMaxDynamicSharedMemorySize, GSM_TOTAL);
    cudaFuncSetAttribute(gemm_wmma_kernel<true,  false, true >, cudaFuncAttributeMaxDynamicSharedMemorySize, GSM_TOTAL);
    cudaFuncSetAttribute(gemm_wmma_kernel<true,  false, false>, cudaFuncAttributeMaxDynamicSharedMemorySize, GSM_TOTAL);
    cudaFuncSetAttribute(head_wmma_kernel, cudaFuncAttributeMaxDynamicSharedMemorySize, HSM_TOTAL);

    const int edgeGrid = (EE + 255) / 256;
    const int aggGrid  = (NN + 7) / 8;
    const int tcGrid   = (NN + 127) / 128;
    const size_t wpage = (size_t)128 * WLD;

    prep_w_kernel<<<50, 256>>>(W1a, W2a, W1b, W2b, Wl1, Wl2);   // also zeroes g_deg
    hist_kernel<<<edgeGrid, 256>>>(ei);
    scan_kernel<<<1, 1024>>>();
    fill_kernel<<<edgeGrid, 256>>>(ei);
#define WHI(p) (wt + (size_t)(p) * 2 * wpage)
#define WLO(p) (wt + (size_t)(p) * 2 * wpage + wpage)

    // ---- conv1 ----
    aggregate_kernel<<<aggGrid, 256>>>(x, pA);
    gemm_wmma_kernel<false, true, false><<<tcGrid, 256, GSM_TOTAL>>>(
        pA, WHI(0), WLO(0), b1a, nullptr, nullptr, pB, NN);
    gemm_wmma_kernel<true, false, true><<<tcGrid, 256, GSM_TOTAL>>>(
        pB, WHI(1), WLO(1), b2a, g1, be1, pC, NN);

    // ---- conv2 ----
    aggregate_kernel<<<aggGrid, 256>>>(pC, pA);
    gemm_wmma_kernel<false, true, false><<<tcGrid, 256, GSM_TOTAL>>>(
        pA, WHI(2), WLO(2), b1b, nullptr, nullptr, pB, NN);
    gemm_wmma_kernel<true, false, true><<<tcGrid, 256, GSM_TOTAL>>>(
        pB, WHI(3), WLO(3), b2b, g2, be2, pC, NN);

    // ---- head ----
    gemm_wmma_kernel<true, false, false><<<tcGrid, 256, GSM_TOTAL>>>(
        pC, WHI(4), WLO(4), bl1, nullptr, nullptr, pA, NN);
    head_wmma_kernel<<<tcGrid, 256, HSM_TOTAL>>>(pA, bl2, out, NN);
}